// round 1
// baseline (speedup 1.0000x reference)
#include <cuda_runtime.h>
#include <cstddef>

// Problem constants
constexpr int N_  = 25000;   // nodes
constexpr int E_  = 100000;  // edges
constexpr int H_  = 32;      // hidden
constexpr int NC_ = 8000;    // cliques
constexpr int A_  = 50000;   // node2clique assignments
constexpr int EC_ = 24000;   // clique edges
constexpr int L_  = 2;       // layers
constexpr int HH_ = 1024;    // H*H

// Scratch (device globals; no runtime allocation allowed)
__device__ float g_Y[(size_t)N_ * HH_];   // per-node precomputed Y (reused for cliques)
__device__ float g_z[N_ * H_];
__device__ float g_x[N_ * H_];
__device__ float g_x2[N_ * H_];
__device__ float g_c[NC_ * H_];
__device__ float g_c2[NC_ * H_];
__device__ float g_agg[N_ * H_];
__device__ float g_m[N_ * H_];
__device__ float g_cntE[N_];
__device__ float g_cntCE[NC_];
__device__ float g_cntAc[NC_];
__device__ float g_cntAn[N_];

// ---------------------------------------------------------------------------
__global__ void k_zero(float* __restrict__ p, int n) {
    int i = blockIdx.x * blockDim.x + threadIdx.x;
    if (i < n) p[i] = 0.f;
}

__global__ void k_count(const int* __restrict__ idx, float* __restrict__ cnt, int n) {
    int i = blockIdx.x * blockDim.x + threadIdx.x;
    if (i < n) atomicAdd(&cnt[idx[i]], 1.f);
}

// Y[n, k*32+o] = sum_i x[n,i] * W2[k*1024 + i*32 + o]
// z[n, o]      = sum_i x[n,i] * b2[i*32 + o]
// Block: 256 threads, 64 rows per block. Full W2 (128KB) staged in smem.
__global__ __launch_bounds__(256) void k_Y(
    const float* __restrict__ x, const float* __restrict__ W2,
    const float* __restrict__ b2, float* __restrict__ Y,
    float* __restrict__ z, int rows)
{
    extern __shared__ float sm[];
    float* W2s = sm;                 // 32768
    float* b2s = sm + 32768;         // 1024
    float* xs  = sm + 33792;         // 64*32

    int tid = threadIdx.x;
    {   // stage W2 + b2 (float4)
        const float4* s4 = (const float4*)W2;
        float4* d4 = (float4*)W2s;
        for (int i = tid; i < 8192; i += 256) d4[i] = s4[i];
        const float4* b4 = (const float4*)b2;
        float4* bd = (float4*)b2s;
        if (tid < 256) bd[tid] = b4[tid];
    }
    int n0 = blockIdx.x * 64;
    for (int i = tid; i < 64 * 32; i += 256) {
        int r = n0 + (i >> 5);
        xs[i] = (r < rows) ? x[(size_t)r * 32 + (i & 31)] : 0.f;
    }
    __syncthreads();

    int w = tid >> 5, lane = tid & 31;
    int nb = w * 8;                         // 8 rows per warp
    const float* xp = &xs[nb * 32];

    #pragma unroll
    for (int chunk = 0; chunk < 8; chunk++) {
        int c0 = chunk * 128 + lane * 4;    // 4 consecutive cols, same k-group
        const float* Bp = &W2s[(c0 >> 5) * 1024 + (c0 & 31)];
        float4 acc[8];
        #pragma unroll
        for (int nn = 0; nn < 8; nn++) acc[nn] = make_float4(0.f, 0.f, 0.f, 0.f);
        #pragma unroll 4
        for (int i = 0; i < 32; i++) {
            float4 b = *(const float4*)&Bp[i * 32];
            #pragma unroll
            for (int nn = 0; nn < 8; nn++) {
                float a = xp[nn * 32 + i];
                acc[nn].x += a * b.x; acc[nn].y += a * b.y;
                acc[nn].z += a * b.z; acc[nn].w += a * b.w;
            }
        }
        #pragma unroll
        for (int nn = 0; nn < 8; nn++) {
            int r = n0 + nb + nn;
            if (r < rows) *(float4*)&Y[(size_t)r * 1024 + c0] = acc[nn];
        }
    }
    // z part
    {
        float accz[8];
        #pragma unroll
        for (int nn = 0; nn < 8; nn++) accz[nn] = 0.f;
        #pragma unroll 4
        for (int i = 0; i < 32; i++) {
            float bz = b2s[i * 32 + lane];
            #pragma unroll
            for (int nn = 0; nn < 8; nn++) accz[nn] += xp[nn * 32 + i] * bz;
        }
        #pragma unroll
        for (int nn = 0; nn < 8; nn++) {
            int r = n0 + nb + nn;
            if (r < rows) z[(size_t)r * 32 + lane] = accz[nn];
        }
    }
}

// One warp per edge: h = relu(ef @ w1 + b1); msg_o = z[s,o] + sum_k h_k Y[s,k*32+o];
// atomicAdd into agg[dst].
__global__ __launch_bounds__(256) void k_edge(
    const int* __restrict__ eidx, const float* __restrict__ ef,
    const float* __restrict__ w1, const float* __restrict__ b1,
    const float* __restrict__ Y, const float* __restrict__ z,
    float* __restrict__ agg, int ne)
{
    __shared__ float w1s[8 * 32];
    __shared__ float b1s[32];
    int tid = threadIdx.x;
    if (tid < 256) w1s[tid] = w1[tid];
    if (tid < 32)  b1s[tid] = b1[tid];
    __syncthreads();

    int lane = tid & 31;
    int e = blockIdx.x * 8 + (tid >> 5);
    if (e >= ne) return;

    int s = eidx[e];
    int d = eidx[ne + e];

    float h = b1s[lane];
    const float* efe = &ef[(size_t)e * 8];
    #pragma unroll
    for (int j = 0; j < 8; j++) h += efe[j] * w1s[j * 32 + lane];
    h = fmaxf(h, 0.f);

    float acc = z[(size_t)s * 32 + lane];
    const float* Yr = &Y[(size_t)s * 1024];
    #pragma unroll
    for (int k = 0; k < 32; k++)
        acc += __shfl_sync(0xffffffffu, h, k) * Yr[k * 32 + lane];

    atomicAdd(&agg[(size_t)d * 32 + lane], acc);
}

// out = relu(agg/max(cnt,1) + xin @ rw + rb) ; one warp per row
__global__ __launch_bounds__(256) void k_conv_update(
    const float* __restrict__ xin, const float* __restrict__ agg,
    const float* __restrict__ cnt, const float* __restrict__ rw,
    const float* __restrict__ rb, float* __restrict__ out, int rows)
{
    __shared__ float rws[1024];
    __shared__ float rbs[32];
    int tid = threadIdx.x;
    for (int i = tid; i < 1024; i += 256) rws[i] = rw[i];
    if (tid < 32) rbs[tid] = rb[tid];
    __syncthreads();

    int lane = tid & 31;
    int n = blockIdx.x * 8 + (tid >> 5);
    if (n >= rows) return;

    float xr = xin[(size_t)n * 32 + lane];
    float acc = rbs[lane];
    #pragma unroll
    for (int i = 0; i < 32; i++)
        acc += __shfl_sync(0xffffffffu, xr, i) * rws[i * 32 + lane];
    float inv = 1.f / fmaxf(cnt[n], 1.f);
    acc += agg[(size_t)n * 32 + lane] * inv;
    out[(size_t)n * 32 + lane] = fmaxf(acc, 0.f);
}

// out = in @ W + b ; one warp per row
__global__ __launch_bounds__(256) void k_linear(
    const float* __restrict__ in, const float* __restrict__ W,
    const float* __restrict__ b, float* __restrict__ out, int rows)
{
    __shared__ float Ws[1024];
    __shared__ float bs[32];
    int tid = threadIdx.x;
    for (int i = tid; i < 1024; i += 256) Ws[i] = W[i];
    if (tid < 32) bs[tid] = b[tid];
    __syncthreads();

    int lane = tid & 31;
    int n = blockIdx.x * 8 + (tid >> 5);
    if (n >= rows) return;

    float xr = in[(size_t)n * 32 + lane];
    float acc = bs[lane];
    #pragma unroll
    for (int i = 0; i < 32; i++)
        acc += __shfl_sync(0xffffffffu, xr, i) * Ws[i * 32 + lane];
    out[(size_t)n * 32 + lane] = acc;
}

// One warp per assignment: agg[idx_out[a]] += m[idx_in[a]]
__global__ __launch_bounds__(256) void k_scatter(
    const int* __restrict__ idx_in, const int* __restrict__ idx_out,
    const float* __restrict__ m, float* __restrict__ agg, int n)
{
    int lane = threadIdx.x & 31;
    int a = blockIdx.x * 8 + (threadIdx.x >> 5);
    if (a >= n) return;
    atomicAdd(&agg[(size_t)idx_out[a] * 32 + lane],
              m[(size_t)idx_in[a] * 32 + lane]);
}

// out = base + agg/max(cnt,1) (elementwise over rows*32)
__global__ void k_resid(
    const float* __restrict__ base, const float* __restrict__ agg,
    const float* __restrict__ cnt, float* __restrict__ out, int rows)
{
    int i = blockIdx.x * blockDim.x + threadIdx.x;
    if (i >= rows * 32) return;
    int n = i >> 5;
    out[i] = base[i] + agg[i] / fmaxf(cnt[n], 1.f);
}

// ---------------------------------------------------------------------------
static inline int cdiv(int a, int b) { return (a + b - 1) / b; }

extern "C" void kernel_launch(void* const* d_in, const int* in_sizes, int n_in,
                              void* d_out, int out_size)
{
    const float* node_features   = (const float*)d_in[0];
    const int*   edge_index      = (const int*)d_in[1];
    const float* edge_features   = (const float*)d_in[2];
    const float* clique_features = (const float*)d_in[3];
    const int*   n2c_index       = (const int*)d_in[4];   // [2, A]: nid, cid
    const int*   cedge_index     = (const int*)d_in[5];
    const float* cedge_features  = (const float*)d_in[6];
    const float* nn1_w  = (const float*)d_in[7];
    const float* nn1_b  = (const float*)d_in[8];
    const float* nn2_w  = (const float*)d_in[9];
    const float* nn2_b  = (const float*)d_in[10];
    const float* root_w = (const float*)d_in[11];
    const float* root_b = (const float*)d_in[12];
    const float* n2c_w  = (const float*)d_in[13];
    const float* n2c_b  = (const float*)d_in[14];
    const float* cnn1_w = (const float*)d_in[15];
    const float* cnn1_b = (const float*)d_in[16];
    const float* cnn2_w = (const float*)d_in[17];
    const float* cnn2_b = (const float*)d_in[18];
    const float* croot_w = (const float*)d_in[19];
    const float* croot_b = (const float*)d_in[20];
    const float* c2n_w  = (const float*)d_in[21];
    const float* c2n_b  = (const float*)d_in[22];

    float *Y, *z, *x, *x2, *c, *c2, *agg, *m, *cntE, *cntCE, *cntAc, *cntAn;
    cudaGetSymbolAddress((void**)&Y, g_Y);
    cudaGetSymbolAddress((void**)&z, g_z);
    cudaGetSymbolAddress((void**)&x, g_x);
    cudaGetSymbolAddress((void**)&x2, g_x2);
    cudaGetSymbolAddress((void**)&c, g_c);
    cudaGetSymbolAddress((void**)&c2, g_c2);
    cudaGetSymbolAddress((void**)&agg, g_agg);
    cudaGetSymbolAddress((void**)&m, g_m);
    cudaGetSymbolAddress((void**)&cntE, g_cntE);
    cudaGetSymbolAddress((void**)&cntCE, g_cntCE);
    cudaGetSymbolAddress((void**)&cntAc, g_cntAc);
    cudaGetSymbolAddress((void**)&cntAn, g_cntAn);

    const int SMEM_Y = (32768 + 1024 + 64 * 32) * 4;
    cudaFuncSetAttribute(k_Y, cudaFuncAttributeMaxDynamicSharedMemorySize, SMEM_Y);

    // init state
    cudaMemcpyAsync(x, node_features, (size_t)N_ * H_ * 4, cudaMemcpyDeviceToDevice, 0);
    cudaMemcpyAsync(c, clique_features, (size_t)NC_ * H_ * 4, cudaMemcpyDeviceToDevice, 0);

    // counts (fixed across layers)
    k_zero<<<cdiv(N_, 256), 256>>>(cntE, N_);
    k_zero<<<cdiv(NC_, 256), 256>>>(cntCE, NC_);
    k_zero<<<cdiv(NC_, 256), 256>>>(cntAc, NC_);
    k_zero<<<cdiv(N_, 256), 256>>>(cntAn, N_);
    k_count<<<cdiv(E_, 256), 256>>>(edge_index + E_, cntE, E_);
    k_count<<<cdiv(EC_, 256), 256>>>(cedge_index + EC_, cntCE, EC_);
    k_count<<<cdiv(A_, 256), 256>>>(n2c_index + A_, cntAc, A_);
    k_count<<<cdiv(A_, 256), 256>>>(n2c_index, cntAn, A_);

    for (int l = 0; l < L_; l++) {
        // ---- node NNConv: x2 = relu(nnconv(x)) ----
        k_Y<<<cdiv(N_, 64), 256, SMEM_Y>>>(x, nn2_w + (size_t)l * 32768,
                                           nn2_b + (size_t)l * 1024, Y, z, N_);
        k_zero<<<cdiv(N_ * 32, 256), 256>>>(agg, N_ * 32);
        k_edge<<<cdiv(E_, 8), 256>>>(edge_index, edge_features,
                                     nn1_w + (size_t)l * 256, nn1_b + (size_t)l * 32,
                                     Y, z, agg, E_);
        k_conv_update<<<cdiv(N_, 8), 256>>>(x, agg, cntE,
                                            root_w + (size_t)l * 1024,
                                            root_b + (size_t)l * 32, x2, N_);
        // ---- Node2Clique: c2 = c + segmean((x2@W+b)[nid] -> cid) ----
        k_linear<<<cdiv(N_, 8), 256>>>(x2, n2c_w + (size_t)l * 1024,
                                       n2c_b + (size_t)l * 32, m, N_);
        k_zero<<<cdiv(NC_ * 32, 256), 256>>>(agg, NC_ * 32);
        k_scatter<<<cdiv(A_, 8), 256>>>(n2c_index, n2c_index + A_, m, agg, A_);
        k_resid<<<cdiv(NC_ * 32, 256), 256>>>(c, agg, cntAc, c2, NC_);
        // ---- clique NNConv: c = relu(nnconv(c2)) ----
        k_Y<<<cdiv(NC_, 64), 256, SMEM_Y>>>(c2, cnn2_w + (size_t)l * 32768,
                                            cnn2_b + (size_t)l * 1024, Y, z, NC_);
        k_zero<<<cdiv(NC_ * 32, 256), 256>>>(agg, NC_ * 32);
        k_edge<<<cdiv(EC_, 8), 256>>>(cedge_index, cedge_features,
                                      cnn1_w + (size_t)l * 256, cnn1_b + (size_t)l * 32,
                                      Y, z, agg, EC_);
        k_conv_update<<<cdiv(NC_, 8), 256>>>(c2, agg, cntCE,
                                             croot_w + (size_t)l * 1024,
                                             croot_b + (size_t)l * 32, c, NC_);
        // ---- Clique2Node: x = x2 + segmean((c@W+b)[cid] -> nid) ----
        k_linear<<<cdiv(NC_, 8), 256>>>(c, c2n_w + (size_t)l * 1024,
                                        c2n_b + (size_t)l * 32, m, NC_);
        k_zero<<<cdiv(N_ * 32, 256), 256>>>(agg, N_ * 32);
        k_scatter<<<cdiv(A_, 8), 256>>>(n2c_index + A_, n2c_index, m, agg, A_);
        k_resid<<<cdiv(N_ * 32, 256), 256>>>(x2, agg, cntAn, x, N_);
    }

    // output: [x (N*H), c (NC*H)] float32
    cudaMemcpyAsync(d_out, x, (size_t)N_ * H_ * 4, cudaMemcpyDeviceToDevice, 0);
    cudaMemcpyAsync((float*)d_out + (size_t)N_ * H_, c, (size_t)NC_ * H_ * 4,
                    cudaMemcpyDeviceToDevice, 0);
}

// round 2
// speedup vs baseline: 1.4150x; 1.4150x over previous
#include <cuda_runtime.h>
#include <cstddef>

// Problem constants
constexpr int N_  = 25000;   // nodes
constexpr int E_  = 100000;  // edges
constexpr int H_  = 32;      // hidden
constexpr int NC_ = 8000;    // cliques
constexpr int A_  = 50000;   // node2clique assignments
constexpr int EC_ = 24000;   // clique edges
constexpr int L_  = 2;       // layers
constexpr int HH_ = 1024;    // H*H

// Scratch (device globals; no runtime allocation allowed)
__device__ float g_Y[(size_t)N_ * HH_];   // per-node precomputed Y (reused for cliques)
__device__ float g_z[N_ * H_];
__device__ float g_x[N_ * H_];
__device__ float g_x2[N_ * H_];
__device__ float g_c[NC_ * H_];
__device__ float g_c2[NC_ * H_];
__device__ float g_agg[N_ * H_];
__device__ float g_m[N_ * H_];
__device__ float g_cntE[N_];
__device__ float g_cntCE[NC_];
__device__ float g_cntAc[NC_];
__device__ float g_cntAn[N_];

// ---------------------------------------------------------------------------
__global__ void k_zero(float* __restrict__ p, int n) {
    int i = blockIdx.x * blockDim.x + threadIdx.x;
    if (i < n) p[i] = 0.f;
}

__global__ void k_count(const int* __restrict__ idx, float* __restrict__ cnt, int n) {
    int i = blockIdx.x * blockDim.x + threadIdx.x;
    if (i < n) atomicAdd(&cnt[idx[i]], 1.f);
}

// Y[n, k*32+o] = sum_i x[n,i] * W2[k*1024 + i*32 + o]
// z[n, o]      = sum_i x[n,i] * b2[i*32 + o]
// Block: 256 threads, 64 rows per block. Full W2 (128KB) staged in smem.
__global__ __launch_bounds__(256) void k_Y(
    const float* __restrict__ x, const float* __restrict__ W2,
    const float* __restrict__ b2, float* __restrict__ Y,
    float* __restrict__ z, int rows)
{
    extern __shared__ float sm[];
    float* W2s = sm;                 // 32768
    float* b2s = sm + 32768;         // 1024
    float* xs  = sm + 33792;         // 64*32

    int tid = threadIdx.x;
    {   // stage W2 + b2 (float4)
        const float4* s4 = (const float4*)W2;
        float4* d4 = (float4*)W2s;
        for (int i = tid; i < 8192; i += 256) d4[i] = s4[i];
        const float4* b4 = (const float4*)b2;
        float4* bd = (float4*)b2s;
        if (tid < 256) bd[tid] = b4[tid];
    }
    int n0 = blockIdx.x * 64;
    for (int i = tid; i < 64 * 32; i += 256) {
        int r = n0 + (i >> 5);
        xs[i] = (r < rows) ? x[(size_t)r * 32 + (i & 31)] : 0.f;
    }
    __syncthreads();

    int w = tid >> 5, lane = tid & 31;
    int nb = w * 8;                         // 8 rows per warp
    const float* xp = &xs[nb * 32];

    #pragma unroll
    for (int chunk = 0; chunk < 8; chunk++) {
        int c0 = chunk * 128 + lane * 4;    // 4 consecutive cols, same k-group
        const float* Bp = &W2s[(c0 >> 5) * 1024 + (c0 & 31)];
        float4 acc[8];
        #pragma unroll
        for (int nn = 0; nn < 8; nn++) acc[nn] = make_float4(0.f, 0.f, 0.f, 0.f);
        #pragma unroll 4
        for (int i = 0; i < 32; i++) {
            float4 b = *(const float4*)&Bp[i * 32];
            #pragma unroll
            for (int nn = 0; nn < 8; nn++) {
                float a = xp[nn * 32 + i];
                acc[nn].x += a * b.x; acc[nn].y += a * b.y;
                acc[nn].z += a * b.z; acc[nn].w += a * b.w;
            }
        }
        #pragma unroll
        for (int nn = 0; nn < 8; nn++) {
            int r = n0 + nb + nn;
            if (r < rows) *(float4*)&Y[(size_t)r * 1024 + c0] = acc[nn];
        }
    }
    // z part
    {
        float accz[8];
        #pragma unroll
        for (int nn = 0; nn < 8; nn++) accz[nn] = 0.f;
        #pragma unroll 4
        for (int i = 0; i < 32; i++) {
            float bz = b2s[i * 32 + lane];
            #pragma unroll
            for (int nn = 0; nn < 8; nn++) accz[nn] += xp[nn * 32 + i] * bz;
        }
        #pragma unroll
        for (int nn = 0; nn < 8; nn++) {
            int r = n0 + nb + nn;
            if (r < rows) z[(size_t)r * 32 + lane] = accz[nn];
        }
    }
}

// One warp per edge: h = relu(ef @ w1 + b1); msg_o = z[s,o] + sum_k h_k Y[s,k*32+o];
// atomicAdd into agg[dst].
__global__ __launch_bounds__(256) void k_edge(
    const int* __restrict__ eidx, const float* __restrict__ ef,
    const float* __restrict__ w1, const float* __restrict__ b1,
    const float* __restrict__ Y, const float* __restrict__ z,
    float* __restrict__ agg, int ne)
{
    __shared__ float w1s[8 * 32];
    __shared__ float b1s[32];
    int tid = threadIdx.x;
    if (tid < 256) w1s[tid] = w1[tid];
    if (tid < 32)  b1s[tid] = b1[tid];
    __syncthreads();

    int lane = tid & 31;
    int e = blockIdx.x * 8 + (tid >> 5);
    if (e >= ne) return;

    int s = eidx[e];
    int d = eidx[ne + e];

    float h = b1s[lane];
    const float* efe = &ef[(size_t)e * 8];
    #pragma unroll
    for (int j = 0; j < 8; j++) h += efe[j] * w1s[j * 32 + lane];
    h = fmaxf(h, 0.f);

    float acc = z[(size_t)s * 32 + lane];
    const float* Yr = &Y[(size_t)s * 1024];
    #pragma unroll
    for (int k = 0; k < 32; k++)
        acc += __shfl_sync(0xffffffffu, h, k) * Yr[k * 32 + lane];

    atomicAdd(&agg[(size_t)d * 32 + lane], acc);
}

// out = relu(agg/max(cnt,1) + xin @ rw + rb) ; one warp per row
__global__ __launch_bounds__(256) void k_conv_update(
    const float* __restrict__ xin, const float* __restrict__ agg,
    const float* __restrict__ cnt, const float* __restrict__ rw,
    const float* __restrict__ rb, float* __restrict__ out, int rows)
{
    __shared__ float rws[1024];
    __shared__ float rbs[32];
    int tid = threadIdx.x;
    for (int i = tid; i < 1024; i += 256) rws[i] = rw[i];
    if (tid < 32) rbs[tid] = rb[tid];
    __syncthreads();

    int lane = tid & 31;
    int n = blockIdx.x * 8 + (tid >> 5);
    if (n >= rows) return;

    float xr = xin[(size_t)n * 32 + lane];
    float acc = rbs[lane];
    #pragma unroll
    for (int i = 0; i < 32; i++)
        acc += __shfl_sync(0xffffffffu, xr, i) * rws[i * 32 + lane];
    float inv = 1.f / fmaxf(cnt[n], 1.f);
    acc += agg[(size_t)n * 32 + lane] * inv;
    out[(size_t)n * 32 + lane] = fmaxf(acc, 0.f);
}

// out = in @ W + b ; one warp per row
__global__ __launch_bounds__(256) void k_linear(
    const float* __restrict__ in, const float* __restrict__ W,
    const float* __restrict__ b, float* __restrict__ out, int rows)
{
    __shared__ float Ws[1024];
    __shared__ float bs[32];
    int tid = threadIdx.x;
    for (int i = tid; i < 1024; i += 256) Ws[i] = W[i];
    if (tid < 32) bs[tid] = b[tid];
    __syncthreads();

    int lane = tid & 31;
    int n = blockIdx.x * 8 + (tid >> 5);
    if (n >= rows) return;

    float xr = in[(size_t)n * 32 + lane];
    float acc = bs[lane];
    #pragma unroll
    for (int i = 0; i < 32; i++)
        acc += __shfl_sync(0xffffffffu, xr, i) * Ws[i * 32 + lane];
    out[(size_t)n * 32 + lane] = acc;
}

// One warp per assignment: agg[idx_out[a]] += m[idx_in[a]]
__global__ __launch_bounds__(256) void k_scatter(
    const int* __restrict__ idx_in, const int* __restrict__ idx_out,
    const float* __restrict__ m, float* __restrict__ agg, int n)
{
    int lane = threadIdx.x & 31;
    int a = blockIdx.x * 8 + (threadIdx.x >> 5);
    if (a >= n) return;
    atomicAdd(&agg[(size_t)idx_out[a] * 32 + lane],
              m[(size_t)idx_in[a] * 32 + lane]);
}

// out = base + agg/max(cnt,1) (elementwise over rows*32)
__global__ void k_resid(
    const float* __restrict__ base, const float* __restrict__ agg,
    const float* __restrict__ cnt, float* __restrict__ out, int rows)
{
    int i = blockIdx.x * blockDim.x + threadIdx.x;
    if (i >= rows * 32) return;
    int n = i >> 5;
    out[i] = base[i] + agg[i] / fmaxf(cnt[n], 1.f);
}

// ---------------------------------------------------------------------------
static inline int cdiv(int a, int b) { return (a + b - 1) / b; }

extern "C" void kernel_launch(void* const* d_in, const int* in_sizes, int n_in,
                              void* d_out, int out_size)
{
    const float* node_features   = (const float*)d_in[0];
    const int*   edge_index      = (const int*)d_in[1];
    const float* edge_features   = (const float*)d_in[2];
    const float* clique_features = (const float*)d_in[3];
    const int*   n2c_index       = (const int*)d_in[4];   // [2, A]: nid, cid
    const int*   cedge_index     = (const int*)d_in[5];
    const float* cedge_features  = (const float*)d_in[6];
    const float* nn1_w  = (const float*)d_in[7];
    const float* nn1_b  = (const float*)d_in[8];
    const float* nn2_w  = (const float*)d_in[9];
    const float* nn2_b  = (const float*)d_in[10];
    const float* root_w = (const float*)d_in[11];
    const float* root_b = (const float*)d_in[12];
    const float* n2c_w  = (const float*)d_in[13];
    const float* n2c_b  = (const float*)d_in[14];
    const float* cnn1_w = (const float*)d_in[15];
    const float* cnn1_b = (const float*)d_in[16];
    const float* cnn2_w = (const float*)d_in[17];
    const float* cnn2_b = (const float*)d_in[18];
    const float* croot_w = (const float*)d_in[19];
    const float* croot_b = (const float*)d_in[20];
    const float* c2n_w  = (const float*)d_in[21];
    const float* c2n_b  = (const float*)d_in[22];

    float *Y, *z, *x, *x2, *c, *c2, *agg, *m, *cntE, *cntCE, *cntAc, *cntAn;
    cudaGetSymbolAddress((void**)&Y, g_Y);
    cudaGetSymbolAddress((void**)&z, g_z);
    cudaGetSymbolAddress((void**)&x, g_x);
    cudaGetSymbolAddress((void**)&x2, g_x2);
    cudaGetSymbolAddress((void**)&c, g_c);
    cudaGetSymbolAddress((void**)&c2, g_c2);
    cudaGetSymbolAddress((void**)&agg, g_agg);
    cudaGetSymbolAddress((void**)&m, g_m);
    cudaGetSymbolAddress((void**)&cntE, g_cntE);
    cudaGetSymbolAddress((void**)&cntCE, g_cntCE);
    cudaGetSymbolAddress((void**)&cntAc, g_cntAc);
    cudaGetSymbolAddress((void**)&cntAn, g_cntAn);

    const int SMEM_Y = (32768 + 1024 + 64 * 32) * 4;
    cudaFuncSetAttribute(k_Y, cudaFuncAttributeMaxDynamicSharedMemorySize, SMEM_Y);

    // init state
    cudaMemcpyAsync(x, node_features, (size_t)N_ * H_ * 4, cudaMemcpyDeviceToDevice, 0);
    cudaMemcpyAsync(c, clique_features, (size_t)NC_ * H_ * 4, cudaMemcpyDeviceToDevice, 0);

    // counts (fixed across layers)
    k_zero<<<cdiv(N_, 256), 256>>>(cntE, N_);
    k_zero<<<cdiv(NC_, 256), 256>>>(cntCE, NC_);
    k_zero<<<cdiv(NC_, 256), 256>>>(cntAc, NC_);
    k_zero<<<cdiv(N_, 256), 256>>>(cntAn, N_);
    k_count<<<cdiv(E_, 256), 256>>>(edge_index + E_, cntE, E_);
    k_count<<<cdiv(EC_, 256), 256>>>(cedge_index + EC_, cntCE, EC_);
    k_count<<<cdiv(A_, 256), 256>>>(n2c_index + A_, cntAc, A_);
    k_count<<<cdiv(A_, 256), 256>>>(n2c_index, cntAn, A_);

    for (int l = 0; l < L_; l++) {
        // ---- node NNConv: x2 = relu(nnconv(x)) ----
        k_Y<<<cdiv(N_, 64), 256, SMEM_Y>>>(x, nn2_w + (size_t)l * 32768,
                                           nn2_b + (size_t)l * 1024, Y, z, N_);
        k_zero<<<cdiv(N_ * 32, 256), 256>>>(agg, N_ * 32);
        k_edge<<<cdiv(E_, 8), 256>>>(edge_index, edge_features,
                                     nn1_w + (size_t)l * 256, nn1_b + (size_t)l * 32,
                                     Y, z, agg, E_);
        k_conv_update<<<cdiv(N_, 8), 256>>>(x, agg, cntE,
                                            root_w + (size_t)l * 1024,
                                            root_b + (size_t)l * 32, x2, N_);
        // ---- Node2Clique: c2 = c + segmean((x2@W+b)[nid] -> cid) ----
        k_linear<<<cdiv(N_, 8), 256>>>(x2, n2c_w + (size_t)l * 1024,
                                       n2c_b + (size_t)l * 32, m, N_);
        k_zero<<<cdiv(NC_ * 32, 256), 256>>>(agg, NC_ * 32);
        k_scatter<<<cdiv(A_, 8), 256>>>(n2c_index, n2c_index + A_, m, agg, A_);
        k_resid<<<cdiv(NC_ * 32, 256), 256>>>(c, agg, cntAc, c2, NC_);
        // ---- clique NNConv: c = relu(nnconv(c2)) ----
        k_Y<<<cdiv(NC_, 64), 256, SMEM_Y>>>(c2, cnn2_w + (size_t)l * 32768,
                                            cnn2_b + (size_t)l * 1024, Y, z, NC_);
        k_zero<<<cdiv(NC_ * 32, 256), 256>>>(agg, NC_ * 32);
        k_edge<<<cdiv(EC_, 8), 256>>>(cedge_index, cedge_features,
                                      cnn1_w + (size_t)l * 256, cnn1_b + (size_t)l * 32,
                                      Y, z, agg, EC_);
        k_conv_update<<<cdiv(NC_, 8), 256>>>(c2, agg, cntCE,
                                             croot_w + (size_t)l * 1024,
                                             croot_b + (size_t)l * 32, c, NC_);
        // ---- Clique2Node: x = x2 + segmean((c@W+b)[cid] -> nid) ----
        k_linear<<<cdiv(NC_, 8), 256>>>(c, c2n_w + (size_t)l * 1024,
                                        c2n_b + (size_t)l * 32, m, NC_);
        k_zero<<<cdiv(N_ * 32, 256), 256>>>(agg, N_ * 32);
        k_scatter<<<cdiv(A_, 8), 256>>>(n2c_index + A_, n2c_index, m, agg, A_);
        k_resid<<<cdiv(N_ * 32, 256), 256>>>(x2, agg, cntAn, x, N_);
    }

    // output: [x (N*H), c (NC*H)] float32
    cudaMemcpyAsync(d_out, x, (size_t)N_ * H_ * 4, cudaMemcpyDeviceToDevice, 0);
    cudaMemcpyAsync((float*)d_out + (size_t)N_ * H_, c, (size_t)NC_ * H_ * 4,
                    cudaMemcpyDeviceToDevice, 0);
}

// round 3
// speedup vs baseline: 1.4440x; 1.0205x over previous
#include <cuda_runtime.h>
#include <cstddef>

// Problem constants
constexpr int N_  = 25000;   // nodes
constexpr int E_  = 100000;  // edges
constexpr int H_  = 32;      // hidden
constexpr int NC_ = 8000;    // cliques
constexpr int A_  = 50000;   // node2clique assignments
constexpr int EC_ = 24000;   // clique edges
constexpr int L_  = 2;       // layers
constexpr int HH_ = 1024;    // H*H

// Scratch (device globals; no runtime allocation allowed)
__device__ float g_Y[(size_t)N_ * HH_];
__device__ float g_z[N_ * H_];
__device__ float g_x[N_ * H_];
__device__ float g_x2[N_ * H_];
__device__ float g_c[NC_ * H_];
__device__ float g_c2[NC_ * H_];
__device__ float g_agg[N_ * H_];
__device__ float g_m[N_ * H_];
__device__ float g_cntE[N_];
__device__ float g_cntCE[NC_];
__device__ float g_cntAc[NC_];
__device__ float g_cntAn[N_];

// ---------------------------------------------------------------------------
// Setup: zero all count arrays + agg (one kernel)
__global__ void k_zero_all(float* __restrict__ cntE, float* __restrict__ cntCE,
                           float* __restrict__ cntAc, float* __restrict__ cntAn,
                           float* __restrict__ agg)
{
    int i = blockIdx.x * blockDim.x + threadIdx.x;
    int stride = gridDim.x * blockDim.x;
    for (int j = i; j < N_; j += stride) { cntE[j] = 0.f; cntAn[j] = 0.f; }
    for (int j = i; j < NC_; j += stride) { cntCE[j] = 0.f; cntAc[j] = 0.f; }
    for (int j = i; j < N_ * H_; j += stride) agg[j] = 0.f;
}

// Setup: all 4 counting passes (one kernel)
__global__ void k_count_all(const int* __restrict__ edst, const int* __restrict__ cedst,
                            const int* __restrict__ nid, const int* __restrict__ cid,
                            float* __restrict__ cntE, float* __restrict__ cntCE,
                            float* __restrict__ cntAc, float* __restrict__ cntAn)
{
    constexpr int T0 = E_, T1 = E_ + EC_, T2 = E_ + EC_ + A_, T3 = E_ + EC_ + A_ + A_;
    int i = blockIdx.x * blockDim.x + threadIdx.x;
    int stride = gridDim.x * blockDim.x;
    for (int j = i; j < T3; j += stride) {
        if (j < T0)      atomicAdd(&cntE[edst[j]], 1.f);
        else if (j < T1) atomicAdd(&cntCE[cedst[j - T0]], 1.f);
        else if (j < T2) atomicAdd(&cntAc[cid[j - T1]], 1.f);
        else             atomicAdd(&cntAn[nid[j - T2]], 1.f);
    }
}

// Y[n, k*32+o] = sum_i x[n,i] * W2[k*1024 + i*32 + o]
// z[n, o]      = sum_i x[n,i] * b2[i*32 + o]
__global__ __launch_bounds__(256) void k_Y(
    const float* __restrict__ x, const float* __restrict__ W2,
    const float* __restrict__ b2, float* __restrict__ Y,
    float* __restrict__ z, int rows)
{
    extern __shared__ float sm[];
    float* W2s = sm;                 // 32768
    float* b2s = sm + 32768;         // 1024
    float* xs  = sm + 33792;         // 64*32

    int tid = threadIdx.x;
    {
        const float4* s4 = (const float4*)W2;
        float4* d4 = (float4*)W2s;
        for (int i = tid; i < 8192; i += 256) d4[i] = s4[i];
        const float4* b4 = (const float4*)b2;
        float4* bd = (float4*)b2s;
        if (tid < 256) bd[tid] = b4[tid];
    }
    int n0 = blockIdx.x * 64;
    for (int i = tid; i < 64 * 32; i += 256) {
        int r = n0 + (i >> 5);
        xs[i] = (r < rows) ? x[(size_t)r * 32 + (i & 31)] : 0.f;
    }
    __syncthreads();

    int w = tid >> 5, lane = tid & 31;
    int nb = w * 8;
    const float* xp = &xs[nb * 32];

    #pragma unroll
    for (int chunk = 0; chunk < 8; chunk++) {
        int c0 = chunk * 128 + lane * 4;
        const float* Bp = &W2s[(c0 >> 5) * 1024 + (c0 & 31)];
        float4 acc[8];
        #pragma unroll
        for (int nn = 0; nn < 8; nn++) acc[nn] = make_float4(0.f, 0.f, 0.f, 0.f);
        #pragma unroll 4
        for (int i = 0; i < 32; i++) {
            float4 b = *(const float4*)&Bp[i * 32];
            #pragma unroll
            for (int nn = 0; nn < 8; nn++) {
                float a = xp[nn * 32 + i];
                acc[nn].x += a * b.x; acc[nn].y += a * b.y;
                acc[nn].z += a * b.z; acc[nn].w += a * b.w;
            }
        }
        #pragma unroll
        for (int nn = 0; nn < 8; nn++) {
            int r = n0 + nb + nn;
            if (r < rows) *(float4*)&Y[(size_t)r * 1024 + c0] = acc[nn];
        }
    }
    {
        float accz[8];
        #pragma unroll
        for (int nn = 0; nn < 8; nn++) accz[nn] = 0.f;
        #pragma unroll 4
        for (int i = 0; i < 32; i++) {
            float bz = b2s[i * 32 + lane];
            #pragma unroll
            for (int nn = 0; nn < 8; nn++) accz[nn] += xp[nn * 32 + i] * bz;
        }
        #pragma unroll
        for (int nn = 0; nn < 8; nn++) {
            int r = n0 + nb + nn;
            if (r < rows) z[(size_t)r * 32 + lane] = accz[nn];
        }
    }
}

// One warp per edge: h = relu(ef @ w1 + b1); msg_o = z[s,o] + sum_k h_k Y[s,k*32+o];
// atomicAdd into agg[dst].
__global__ __launch_bounds__(256) void k_edge(
    const int* __restrict__ eidx, const float* __restrict__ ef,
    const float* __restrict__ w1, const float* __restrict__ b1,
    const float* __restrict__ Y, const float* __restrict__ z,
    float* __restrict__ agg, int ne)
{
    __shared__ float w1s[8 * 32];
    __shared__ float b1s[32];
    int tid = threadIdx.x;
    if (tid < 256) w1s[tid] = w1[tid];
    if (tid < 32)  b1s[tid] = b1[tid];
    __syncthreads();

    int lane = tid & 31;
    int e = blockIdx.x * 8 + (tid >> 5);
    if (e >= ne) return;

    int s = eidx[e];
    int d = eidx[ne + e];

    float h = b1s[lane];
    const float* efe = &ef[(size_t)e * 8];
    #pragma unroll
    for (int j = 0; j < 8; j++) h += efe[j] * w1s[j * 32 + lane];
    h = fmaxf(h, 0.f);

    float acc = z[(size_t)s * 32 + lane];
    const float* Yr = &Y[(size_t)s * 1024];
    #pragma unroll
    for (int k = 0; k < 32; k++)
        acc += __shfl_sync(0xffffffffu, h, k) * Yr[k * 32 + lane];

    atomicAdd(&agg[(size_t)d * 32 + lane], acc);
}

// Fused: out = relu(agg/cnt + xin @ rw + rb) ; mout = out @ lw + lb
// Also clears agg (consume-and-clear). One warp per row.
__global__ __launch_bounds__(256) void k_convlin(
    const float* __restrict__ xin, float* __restrict__ agg,
    const float* __restrict__ cnt,
    const float* __restrict__ rw, const float* __restrict__ rb,
    const float* __restrict__ lw, const float* __restrict__ lb,
    float* __restrict__ out, float* __restrict__ mout, int rows)
{
    __shared__ float rws[1024], lws[1024];
    __shared__ float rbs[32], lbs[32];
    int tid = threadIdx.x;
    for (int i = tid; i < 1024; i += 256) { rws[i] = rw[i]; lws[i] = lw[i]; }
    if (tid < 32) { rbs[tid] = rb[tid]; lbs[tid] = lb[tid]; }
    __syncthreads();

    int lane = tid & 31;
    int n = blockIdx.x * 8 + (tid >> 5);
    if (n >= rows) return;

    size_t base = (size_t)n * 32 + lane;
    float xr = xin[base];
    float acc = rbs[lane];
    #pragma unroll
    for (int i = 0; i < 32; i++)
        acc += __shfl_sync(0xffffffffu, xr, i) * rws[i * 32 + lane];
    float inv = 1.f / fmaxf(cnt[n], 1.f);
    acc += agg[base] * inv;
    agg[base] = 0.f;                       // consume-and-clear
    float o = fmaxf(acc, 0.f);
    out[base] = o;

    float macc = lbs[lane];
    #pragma unroll
    for (int i = 0; i < 32; i++)
        macc += __shfl_sync(0xffffffffu, o, i) * lws[i * 32 + lane];
    mout[base] = macc;
}

// One warp per assignment: agg[idx_out[a]] += m[idx_in[a]]
__global__ __launch_bounds__(256) void k_scatter(
    const int* __restrict__ idx_in, const int* __restrict__ idx_out,
    const float* __restrict__ m, float* __restrict__ agg, int n)
{
    int lane = threadIdx.x & 31;
    int a = blockIdx.x * 8 + (threadIdx.x >> 5);
    if (a >= n) return;
    atomicAdd(&agg[(size_t)idx_out[a] * 32 + lane],
              m[(size_t)idx_in[a] * 32 + lane]);
}

// out = base + agg/max(cnt,1); clears agg. Elementwise over rows*32.
__global__ void k_resid(
    const float* __restrict__ base, float* __restrict__ agg,
    const float* __restrict__ cnt, float* __restrict__ out, int rows)
{
    int i = blockIdx.x * blockDim.x + threadIdx.x;
    if (i >= rows * 32) return;
    int n = i >> 5;
    out[i] = base[i] + agg[i] / fmaxf(cnt[n], 1.f);
    agg[i] = 0.f;                          // consume-and-clear
}

// ---------------------------------------------------------------------------
static inline int cdiv(int a, int b) { return (a + b - 1) / b; }

extern "C" void kernel_launch(void* const* d_in, const int* in_sizes, int n_in,
                              void* d_out, int out_size)
{
    const float* node_features   = (const float*)d_in[0];
    const int*   edge_index      = (const int*)d_in[1];
    const float* edge_features   = (const float*)d_in[2];
    const float* clique_features = (const float*)d_in[3];
    const int*   n2c_index       = (const int*)d_in[4];   // [2, A]: nid, cid
    const int*   cedge_index     = (const int*)d_in[5];
    const float* cedge_features  = (const float*)d_in[6];
    const float* nn1_w  = (const float*)d_in[7];
    const float* nn1_b  = (const float*)d_in[8];
    const float* nn2_w  = (const float*)d_in[9];
    const float* nn2_b  = (const float*)d_in[10];
    const float* root_w = (const float*)d_in[11];
    const float* root_b = (const float*)d_in[12];
    const float* n2c_w  = (const float*)d_in[13];
    const float* n2c_b  = (const float*)d_in[14];
    const float* cnn1_w = (const float*)d_in[15];
    const float* cnn1_b = (const float*)d_in[16];
    const float* cnn2_w = (const float*)d_in[17];
    const float* cnn2_b = (const float*)d_in[18];
    const float* croot_w = (const float*)d_in[19];
    const float* croot_b = (const float*)d_in[20];
    const float* c2n_w  = (const float*)d_in[21];
    const float* c2n_b  = (const float*)d_in[22];

    float *Y, *z, *x, *x2, *c, *c2, *agg, *m, *cntE, *cntCE, *cntAc, *cntAn;
    cudaGetSymbolAddress((void**)&Y, g_Y);
    cudaGetSymbolAddress((void**)&z, g_z);
    cudaGetSymbolAddress((void**)&x, g_x);
    cudaGetSymbolAddress((void**)&x2, g_x2);
    cudaGetSymbolAddress((void**)&c, g_c);
    cudaGetSymbolAddress((void**)&c2, g_c2);
    cudaGetSymbolAddress((void**)&agg, g_agg);
    cudaGetSymbolAddress((void**)&m, g_m);
    cudaGetSymbolAddress((void**)&cntE, g_cntE);
    cudaGetSymbolAddress((void**)&cntCE, g_cntCE);
    cudaGetSymbolAddress((void**)&cntAc, g_cntAc);
    cudaGetSymbolAddress((void**)&cntAn, g_cntAn);

    float* out_x = (float*)d_out;                       // [N, H]
    float* out_c = (float*)d_out + (size_t)N_ * H_;     // [NC, H]

    const int SMEM_Y = (32768 + 1024 + 64 * 32) * 4;
    cudaFuncSetAttribute(k_Y, cudaFuncAttributeMaxDynamicSharedMemorySize, SMEM_Y);

    // Setup (2 launches): zero counts+agg, then counts
    k_zero_all<<<400, 256>>>(cntE, cntCE, cntAc, cntAn, agg);
    k_count_all<<<400, 256>>>(edge_index + E_, cedge_index + EC_,
                              n2c_index, n2c_index + A_,
                              cntE, cntCE, cntAc, cntAn);

    for (int l = 0; l < L_; l++) {
        const float* xin = (l == 0) ? node_features : x;
        const float* cin = (l == 0) ? clique_features : c;
        float* xout = (l == L_ - 1) ? out_x : x;   // final layer writes d_out
        float* cout = (l == L_ - 1) ? out_c : c;

        // ---- node NNConv + fused Node2Clique projection ----
        k_Y<<<cdiv(N_, 64), 256, SMEM_Y>>>(xin, nn2_w + (size_t)l * 32768,
                                           nn2_b + (size_t)l * 1024, Y, z, N_);
        k_edge<<<cdiv(E_, 8), 256>>>(edge_index, edge_features,
                                     nn1_w + (size_t)l * 256, nn1_b + (size_t)l * 32,
                                     Y, z, agg, E_);
        k_convlin<<<cdiv(N_, 8), 256>>>(xin, agg, cntE,
                                        root_w + (size_t)l * 1024, root_b + (size_t)l * 32,
                                        n2c_w + (size_t)l * 1024, n2c_b + (size_t)l * 32,
                                        x2, m, N_);
        // Node2Clique scatter-mean + residual
        k_scatter<<<cdiv(A_, 8), 256>>>(n2c_index, n2c_index + A_, m, agg, A_);
        k_resid<<<cdiv(NC_ * 32, 256), 256>>>(cin, agg, cntAc, c2, NC_);

        // ---- clique NNConv + fused Clique2Node projection ----
        k_Y<<<cdiv(NC_, 64), 256, SMEM_Y>>>(c2, cnn2_w + (size_t)l * 32768,
                                            cnn2_b + (size_t)l * 1024, Y, z, NC_);
        k_edge<<<cdiv(EC_, 8), 256>>>(cedge_index, cedge_features,
                                      cnn1_w + (size_t)l * 256, cnn1_b + (size_t)l * 32,
                                      Y, z, agg, EC_);
        k_convlin<<<cdiv(NC_, 8), 256>>>(c2, agg, cntCE,
                                         croot_w + (size_t)l * 1024, croot_b + (size_t)l * 32,
                                         c2n_w + (size_t)l * 1024, c2n_b + (size_t)l * 32,
                                         cout, m, NC_);
        // Clique2Node scatter-mean + residual
        k_scatter<<<cdiv(A_, 8), 256>>>(n2c_index + A_, n2c_index, m, agg, A_);
        k_resid<<<cdiv(N_ * 32, 256), 256>>>(x2, agg, cntAn, xout, N_);
    }
}

// round 5
// speedup vs baseline: 1.5832x; 1.0964x over previous
#include <cuda_runtime.h>
#include <cuda_fp16.h>
#include <cstddef>

// Problem constants
constexpr int N_  = 25000;   // nodes
constexpr int E_  = 100000;  // edges
constexpr int H_  = 32;      // hidden
constexpr int NC_ = 8000;    // cliques
constexpr int A_  = 50000;   // node2clique assignments
constexpr int EC_ = 24000;   // clique edges
constexpr int L_  = 2;       // layers
constexpr int HH_ = 1024;    // H*H

// Scratch (device globals; no runtime allocation allowed)
// Y stored fp16, pair-interleaved over k: element (k,o) lives at half2
// index (k>>1)*32 + o, component (k&1). 2KB per node row.
__device__ __half g_Yh[(size_t)N_ * HH_];
__device__ float g_z[N_ * H_];
__device__ float g_x[N_ * H_];
__device__ float g_x2[N_ * H_];
__device__ float g_c[NC_ * H_];
__device__ float g_c2[NC_ * H_];
__device__ float g_agg[N_ * H_];
__device__ float g_m[N_ * H_];
__device__ float g_cntE[N_];
__device__ float g_cntCE[NC_];
__device__ float g_cntAc[NC_];
__device__ float g_cntAn[N_];

// ---------------------------------------------------------------------------
__global__ void k_zero_all(float* __restrict__ cntE, float* __restrict__ cntCE,
                           float* __restrict__ cntAc, float* __restrict__ cntAn,
                           float* __restrict__ agg)
{
    int i = blockIdx.x * blockDim.x + threadIdx.x;
    int stride = gridDim.x * blockDim.x;
    for (int j = i; j < N_; j += stride) { cntE[j] = 0.f; cntAn[j] = 0.f; }
    for (int j = i; j < NC_; j += stride) { cntCE[j] = 0.f; cntAc[j] = 0.f; }
    for (int j = i; j < N_ * H_; j += stride) agg[j] = 0.f;
}

__global__ void k_count_all(const int* __restrict__ edst, const int* __restrict__ cedst,
                            const int* __restrict__ nid, const int* __restrict__ cid,
                            float* __restrict__ cntE, float* __restrict__ cntCE,
                            float* __restrict__ cntAc, float* __restrict__ cntAn)
{
    constexpr int T0 = E_, T1 = E_ + EC_, T2 = E_ + EC_ + A_, T3 = E_ + EC_ + A_ + A_;
    int i = blockIdx.x * blockDim.x + threadIdx.x;
    int stride = gridDim.x * blockDim.x;
    for (int j = i; j < T3; j += stride) {
        if (j < T0)      atomicAdd(&cntE[edst[j]], 1.f);
        else if (j < T1) atomicAdd(&cntCE[cedst[j - T0]], 1.f);
        else if (j < T2) atomicAdd(&cntAc[cid[j - T1]], 1.f);
        else             atomicAdd(&cntAn[nid[j - T2]], 1.f);
    }
}

// Y[n, k*32+o] = sum_i x[n,i] * W2[k*1024 + i*32 + o]  (stored fp16 pair-interleaved)
// z[n, o]      = sum_i x[n,i] * b2[i*32 + o]            (fp32)
__global__ __launch_bounds__(256) void k_Y(
    const float* __restrict__ x, const float* __restrict__ W2,
    const float* __restrict__ b2, __half* __restrict__ Yh,
    float* __restrict__ z, int rows)
{
    extern __shared__ float sm[];
    float* W2s = sm;                 // 32768
    float* b2s = sm + 32768;         // 1024
    float* xs  = sm + 33792;         // 64*32

    int tid = threadIdx.x;
    {
        const float4* s4 = (const float4*)W2;
        float4* d4 = (float4*)W2s;
        for (int i = tid; i < 8192; i += 256) d4[i] = s4[i];
        const float4* b4 = (const float4*)b2;
        float4* bd = (float4*)b2s;
        if (tid < 256) bd[tid] = b4[tid];
    }
    int n0 = blockIdx.x * 64;
    for (int i = tid; i < 64 * 32; i += 256) {
        int r = n0 + (i >> 5);
        xs[i] = (r < rows) ? x[(size_t)r * 32 + (i & 31)] : 0.f;
    }
    __syncthreads();

    int w = tid >> 5, lane = tid & 31;
    int nb = w * 8;
    const float* xp = &xs[nb * 32];

    // lane decomposition within a chunk: c0 = chunk*128 + lane*4
    //   k  = chunk*4 + (lane>>3)
    //   o0 = (lane&7)*4
    // partner lane^8 holds (k^1) for the same o0.
    const bool evenk = (lane & 8) == 0;

    #pragma unroll
    for (int chunk = 0; chunk < 8; chunk++) {
        int c0 = chunk * 128 + lane * 4;
        const float* Bp = &W2s[(c0 >> 5) * 1024 + (c0 & 31)];
        float4 acc[8];
        #pragma unroll
        for (int nn = 0; nn < 8; nn++) acc[nn] = make_float4(0.f, 0.f, 0.f, 0.f);
        #pragma unroll 4
        for (int i = 0; i < 32; i++) {
            float4 b = *(const float4*)&Bp[i * 32];
            #pragma unroll
            for (int nn = 0; nn < 8; nn++) {
                float a = xp[nn * 32 + i];
                acc[nn].x += a * b.x; acc[nn].y += a * b.y;
                acc[nn].z += a * b.z; acc[nn].w += a * b.w;
            }
        }
        // pair-exchange with lane^8 and store fp16
        int k = chunk * 4 + (lane >> 3);
        int k2 = k >> 1;                   // pair index
        #pragma unroll
        for (int nn = 0; nn < 8; nn++) {
            float4 a = acc[nn];
            float px = __shfl_xor_sync(0xffffffffu, a.x, 8);
            float py = __shfl_xor_sync(0xffffffffu, a.y, 8);
            float pz = __shfl_xor_sync(0xffffffffu, a.z, 8);
            float pw = __shfl_xor_sync(0xffffffffu, a.w, 8);
            int r = n0 + nb + nn;
            if (evenk && r < rows) {
                union { uint4 u; __half2 h[4]; } val;
                val.h[0] = __halves2half2(__float2half_rn(a.x), __float2half_rn(px));
                val.h[1] = __halves2half2(__float2half_rn(a.y), __float2half_rn(py));
                val.h[2] = __halves2half2(__float2half_rn(a.z), __float2half_rn(pz));
                val.h[3] = __halves2half2(__float2half_rn(a.w), __float2half_rn(pw));
                // half2 index base = k2*32 + (lane&7)*4 ; 4 consecutive half2 = uint4
                uint4* dst = (uint4*)&Yh[(size_t)r * 1024];
                dst[k2 * 8 + (lane & 7)] = val.u;
            }
        }
    }
    // z part (fp32)
    {
        float accz[8];
        #pragma unroll
        for (int nn = 0; nn < 8; nn++) accz[nn] = 0.f;
        #pragma unroll 4
        for (int i = 0; i < 32; i++) {
            float bz = b2s[i * 32 + lane];
            #pragma unroll
            for (int nn = 0; nn < 8; nn++) accz[nn] += xp[nn * 32 + i] * bz;
        }
        #pragma unroll
        for (int nn = 0; nn < 8; nn++) {
            int r = n0 + nb + nn;
            if (r < rows) z[(size_t)r * 32 + lane] = accz[nn];
        }
    }
}

// One warp per edge: h = relu(ef @ w1 + b1);
// msg_o = z[s,o] + sum_k h_k Y[s,(k,o)]  with Y fp16 pair-interleaved.
__global__ __launch_bounds__(256) void k_edge(
    const int* __restrict__ eidx, const float* __restrict__ ef,
    const float* __restrict__ w1, const float* __restrict__ b1,
    const __half* __restrict__ Yh, const float* __restrict__ z,
    float* __restrict__ agg, int ne)
{
    __shared__ float w1s[8 * 32];
    __shared__ float b1s[32];
    int tid = threadIdx.x;
    if (tid < 256) w1s[tid] = w1[tid];
    if (tid < 32)  b1s[tid] = b1[tid];
    __syncthreads();

    int lane = tid & 31;
    int e = blockIdx.x * 8 + (tid >> 5);
    if (e >= ne) return;

    int s = eidx[e];
    int d = eidx[ne + e];

    float h = b1s[lane];
    const float* efe = &ef[(size_t)e * 8];
    #pragma unroll
    for (int j = 0; j < 8; j++) h += efe[j] * w1s[j * 32 + lane];
    h = fmaxf(h, 0.f);

    float acc = z[(size_t)s * 32 + lane];
    const __half2* Yr = (const __half2*)&Yh[(size_t)s * 1024];
    #pragma unroll
    for (int kk = 0; kk < 16; kk++) {
        float2 v = __half22float2(Yr[kk * 32 + lane]);
        acc += __shfl_sync(0xffffffffu, h, 2 * kk)     * v.x;
        acc += __shfl_sync(0xffffffffu, h, 2 * kk + 1) * v.y;
    }

    atomicAdd(&agg[(size_t)d * 32 + lane], acc);
}

// Fused: out = relu(agg/cnt + xin @ rw + rb) ; mout = out @ lw + lb
// Clears agg (consume-and-clear). One warp per row.
__global__ __launch_bounds__(256) void k_convlin(
    const float* __restrict__ xin, float* __restrict__ agg,
    const float* __restrict__ cnt,
    const float* __restrict__ rw, const float* __restrict__ rb,
    const float* __restrict__ lw, const float* __restrict__ lb,
    float* __restrict__ out, float* __restrict__ mout, int rows)
{
    __shared__ float rws[1024], lws[1024];
    __shared__ float rbs[32], lbs[32];
    int tid = threadIdx.x;
    for (int i = tid; i < 1024; i += 256) { rws[i] = rw[i]; lws[i] = lw[i]; }
    if (tid < 32) { rbs[tid] = rb[tid]; lbs[tid] = lb[tid]; }
    __syncthreads();

    int lane = tid & 31;
    int n = blockIdx.x * 8 + (tid >> 5);
    if (n >= rows) return;

    size_t base = (size_t)n * 32 + lane;
    float xr = xin[base];
    float acc = rbs[lane];
    #pragma unroll
    for (int i = 0; i < 32; i++)
        acc += __shfl_sync(0xffffffffu, xr, i) * rws[i * 32 + lane];
    float inv = 1.f / fmaxf(cnt[n], 1.f);
    acc += agg[base] * inv;
    agg[base] = 0.f;
    float o = fmaxf(acc, 0.f);
    out[base] = o;

    float macc = lbs[lane];
    #pragma unroll
    for (int i = 0; i < 32; i++)
        macc += __shfl_sync(0xffffffffu, o, i) * lws[i * 32 + lane];
    mout[base] = macc;
}

// One warp per assignment: agg[idx_out[a]] += m[idx_in[a]]
__global__ __launch_bounds__(256) void k_scatter(
    const int* __restrict__ idx_in, const int* __restrict__ idx_out,
    const float* __restrict__ m, float* __restrict__ agg, int n)
{
    int lane = threadIdx.x & 31;
    int a = blockIdx.x * 8 + (threadIdx.x >> 5);
    if (a >= n) return;
    atomicAdd(&agg[(size_t)idx_out[a] * 32 + lane],
              m[(size_t)idx_in[a] * 32 + lane]);
}

// out = base + agg/max(cnt,1); clears agg.
__global__ void k_resid(
    const float* __restrict__ base, float* __restrict__ agg,
    const float* __restrict__ cnt, float* __restrict__ out, int rows)
{
    int i = blockIdx.x * blockDim.x + threadIdx.x;
    if (i >= rows * 32) return;
    int n = i >> 5;
    out[i] = base[i] + agg[i] / fmaxf(cnt[n], 1.f);
    agg[i] = 0.f;
}

// ---------------------------------------------------------------------------
static inline int cdiv(int a, int b) { return (a + b - 1) / b; }

extern "C" void kernel_launch(void* const* d_in, const int* in_sizes, int n_in,
                              void* d_out, int out_size)
{
    const float* node_features   = (const float*)d_in[0];
    const int*   edge_index      = (const int*)d_in[1];
    const float* edge_features   = (const float*)d_in[2];
    const float* clique_features = (const float*)d_in[3];
    const int*   n2c_index       = (const int*)d_in[4];   // [2, A]: nid, cid
    const int*   cedge_index     = (const int*)d_in[5];
    const float* cedge_features  = (const float*)d_in[6];
    const float* nn1_w  = (const float*)d_in[7];
    const float* nn1_b  = (const float*)d_in[8];
    const float* nn2_w  = (const float*)d_in[9];
    const float* nn2_b  = (const float*)d_in[10];
    const float* root_w = (const float*)d_in[11];
    const float* root_b = (const float*)d_in[12];
    const float* n2c_w  = (const float*)d_in[13];
    const float* n2c_b  = (const float*)d_in[14];
    const float* cnn1_w = (const float*)d_in[15];
    const float* cnn1_b = (const float*)d_in[16];
    const float* cnn2_w = (const float*)d_in[17];
    const float* cnn2_b = (const float*)d_in[18];
    const float* croot_w = (const float*)d_in[19];
    const float* croot_b = (const float*)d_in[20];
    const float* c2n_w  = (const float*)d_in[21];
    const float* c2n_b  = (const float*)d_in[22];

    float *z, *x, *x2, *c, *c2, *agg, *m, *cntE, *cntCE, *cntAc, *cntAn;
    __half* Yh;
    cudaGetSymbolAddress((void**)&Yh, g_Yh);
    cudaGetSymbolAddress((void**)&z, g_z);
    cudaGetSymbolAddress((void**)&x, g_x);
    cudaGetSymbolAddress((void**)&x2, g_x2);
    cudaGetSymbolAddress((void**)&c, g_c);
    cudaGetSymbolAddress((void**)&c2, g_c2);
    cudaGetSymbolAddress((void**)&agg, g_agg);
    cudaGetSymbolAddress((void**)&m, g_m);
    cudaGetSymbolAddress((void**)&cntE, g_cntE);
    cudaGetSymbolAddress((void**)&cntCE, g_cntCE);
    cudaGetSymbolAddress((void**)&cntAc, g_cntAc);
    cudaGetSymbolAddress((void**)&cntAn, g_cntAn);

    float* out_x = (float*)d_out;                       // [N, H]
    float* out_c = (float*)d_out + (size_t)N_ * H_;     // [NC, H]

    const int SMEM_Y = (32768 + 1024 + 64 * 32) * 4;
    cudaFuncSetAttribute(k_Y, cudaFuncAttributeMaxDynamicSharedMemorySize, SMEM_Y);

    k_zero_all<<<400, 256>>>(cntE, cntCE, cntAc, cntAn, agg);
    k_count_all<<<400, 256>>>(edge_index + E_, cedge_index + EC_,
                              n2c_index, n2c_index + A_,
                              cntE, cntCE, cntAc, cntAn);

    for (int l = 0; l < L_; l++) {
        const float* xin = (l == 0) ? node_features : x;
        const float* cin = (l == 0) ? clique_features : c;
        float* xout = (l == L_ - 1) ? out_x : x;
        float* cout = (l == L_ - 1) ? out_c : c;

        // ---- node NNConv + fused Node2Clique projection ----
        k_Y<<<cdiv(N_, 64), 256, SMEM_Y>>>(xin, nn2_w + (size_t)l * 32768,
                                           nn2_b + (size_t)l * 1024, Yh, z, N_);
        k_edge<<<cdiv(E_, 8), 256>>>(edge_index, edge_features,
                                     nn1_w + (size_t)l * 256, nn1_b + (size_t)l * 32,
                                     Yh, z, agg, E_);
        k_convlin<<<cdiv(N_, 8), 256>>>(xin, agg, cntE,
                                        root_w + (size_t)l * 1024, root_b + (size_t)l * 32,
                                        n2c_w + (size_t)l * 1024, n2c_b + (size_t)l * 32,
                                        x2, m, N_);
        k_scatter<<<cdiv(A_, 8), 256>>>(n2c_index, n2c_index + A_, m, agg, A_);
        k_resid<<<cdiv(NC_ * 32, 256), 256>>>(cin, agg, cntAc, c2, NC_);

        // ---- clique NNConv + fused Clique2Node projection ----
        k_Y<<<cdiv(NC_, 64), 256, SMEM_Y>>>(c2, cnn2_w + (size_t)l * 32768,
                                            cnn2_b + (size_t)l * 1024, Yh, z, NC_);
        k_edge<<<cdiv(EC_, 8), 256>>>(cedge_index, cedge_features,
                                      cnn1_w + (size_t)l * 256, cnn1_b + (size_t)l * 32,
                                      Yh, z, agg, EC_);
        k_convlin<<<cdiv(NC_, 8), 256>>>(c2, agg, cntCE,
                                         croot_w + (size_t)l * 1024, croot_b + (size_t)l * 32,
                                         c2n_w + (size_t)l * 1024, c2n_b + (size_t)l * 32,
                                         cout, m, NC_);
        k_scatter<<<cdiv(A_, 8), 256>>>(n2c_index + A_, n2c_index, m, agg, A_);
        k_resid<<<cdiv(N_ * 32, 256), 256>>>(x2, agg, cntAn, xout, N_);
    }
}